// round 4
// baseline (speedup 1.0000x reference)
#include <cuda_runtime.h>
#include <cstdint>

#define MAX_NODES 100000
#define MAX_EDGES 1600000
#define SCAN_B 512

// Scratch (static device globals; no allocation anywhere)
__device__ int   g_count[MAX_NODES];                 // in-degree histogram
__device__ int   g_start[MAX_NODES];                 // CSR row starts (exclusive scan)
__device__ int   g_cursor[MAX_NODES];                // scatter cursors
__device__ int   g_perm_src[MAX_EDGES];              // src node id per dst-sorted edge
__device__ int   g_blocksums[(MAX_NODES + SCAN_B - 1) / SCAN_B];
__device__ int   g_blockoff[(MAX_NODES + SCAN_B - 1) / SCAN_B];
__device__ __align__(16) float g_y[MAX_NODES * 4];   // x1 @ W2_l, padded
__device__ __align__(16) float g_z[MAX_NODES * 4];   // x1 @ W2_r, padded

// ---------------------------------------------------------------------------
// 1) zero histogram
// ---------------------------------------------------------------------------
__global__ void k_zero(int N) {
    int i = blockIdx.x * blockDim.x + threadIdx.x;
    if (i < N) g_count[i] = 0;
}

// ---------------------------------------------------------------------------
// 2) histogram of dst (in-degree)
// ---------------------------------------------------------------------------
__global__ void k_hist(const int* __restrict__ ei, int E, int N) {
    int e = blockIdx.x * blockDim.x + threadIdx.x;
    if (e >= E) return;
    int dst = ei[E + e];
    if ((unsigned)dst < (unsigned)N) atomicAdd(&g_count[dst], 1);
}

// ---------------------------------------------------------------------------
// 3) per-block exclusive scan of g_count -> g_start (local), block totals out
// ---------------------------------------------------------------------------
__global__ void k_scan1(int N) {
    __shared__ int s[SCAN_B];
    int tid = threadIdx.x;
    int i = blockIdx.x * SCAN_B + tid;
    int v = (i < N) ? g_count[i] : 0;
    s[tid] = v;
    __syncthreads();
#pragma unroll
    for (int off = 1; off < SCAN_B; off <<= 1) {
        int t = (tid >= off) ? s[tid - off] : 0;
        __syncthreads();
        s[tid] += t;
        __syncthreads();
    }
    if (i < N) g_start[i] = s[tid] - v;          // exclusive
    if (tid == SCAN_B - 1) g_blocksums[blockIdx.x] = s[tid];
}

// ---------------------------------------------------------------------------
// 4) scan the block sums (single block; works for nb <= SCAN_B)
// ---------------------------------------------------------------------------
__global__ void k_scan2(int nb) {
    __shared__ int s[SCAN_B];
    int tid = threadIdx.x;
    int v = (tid < nb) ? g_blocksums[tid] : 0;
    s[tid] = v;
    __syncthreads();
#pragma unroll
    for (int off = 1; off < SCAN_B; off <<= 1) {
        int t = (tid >= off) ? s[tid - off] : 0;
        __syncthreads();
        s[tid] += t;
        __syncthreads();
    }
    if (tid < nb) g_blockoff[tid] = s[tid] - v;  // exclusive
}

// ---------------------------------------------------------------------------
// 5) add block offsets; init cursors
// ---------------------------------------------------------------------------
__global__ void k_scan3(int N) {
    int i = blockIdx.x * blockDim.x + threadIdx.x;
    if (i >= N) return;
    int st = g_start[i] + g_blockoff[i / SCAN_B];
    g_start[i] = st;
    g_cursor[i] = st;
}

// ---------------------------------------------------------------------------
// 6) scatter src ids into dst-sorted order
// ---------------------------------------------------------------------------
__global__ void k_scatter(const int* __restrict__ ei, int E, int N) {
    int e = blockIdx.x * blockDim.x + threadIdx.x;
    if (e >= E) return;
    int src = ei[e];
    int dst = ei[E + e];
    if ((unsigned)src >= (unsigned)N || (unsigned)dst >= (unsigned)N) return;
    int pos = atomicAdd(&g_cursor[dst], 1);
    g_perm_src[pos] = src;
}

// ---------------------------------------------------------------------------
// 7) fused layer-1: gather-mean + x1 = relu(mean@W1l + b1 + f@W1r),
//    fold to y = x1@W2l, z = x1@W2r. One warp per node.
//    Gather: 8 edge-groups x 4 components; each lane sums one float4.
// ---------------------------------------------------------------------------
__global__ void k_node1(const float4* __restrict__ feat4,
                        const float* __restrict__ feat,
                        const float* __restrict__ W1l,
                        const float* __restrict__ b1,
                        const float* __restrict__ W1r,
                        const float* __restrict__ W2l,
                        const float* __restrict__ W2r, int N) {
    __shared__ float sW1l[16 * 128];
    __shared__ float sW1r[16 * 128];
    __shared__ float sb1[128];
    __shared__ float sW2l[128 * 3];
    __shared__ float sW2r[128 * 3];
    __shared__ float sMean[8][16];          // 8 warps/block

    int tid = threadIdx.x;
    for (int i = tid; i < 2048; i += blockDim.x) { sW1l[i] = W1l[i]; sW1r[i] = W1r[i]; }
    for (int i = tid; i < 128; i += blockDim.x) sb1[i] = b1[i];
    for (int i = tid; i < 384; i += blockDim.x) { sW2l[i] = W2l[i]; sW2r[i] = W2r[i]; }
    __syncthreads();

    int gwarp = (blockIdx.x * blockDim.x + tid) >> 5;
    int lane = tid & 31;
    int warp = tid >> 5;
    if (gwarp >= N) return;
    int n = gwarp;

    int deg = g_count[n];
    int start = g_start[n];
    int egrp = lane >> 2;
    int comp = lane & 3;

    float4 acc = make_float4(0.f, 0.f, 0.f, 0.f);
    for (int j = egrp; j < deg; j += 8) {
        int src = g_perm_src[start + j];
        float4 v = __ldg(&feat4[(size_t)src * 4 + comp]);
        acc.x += v.x; acc.y += v.y; acc.z += v.z; acc.w += v.w;
    }
    // reduce over edge groups (stride-4 lanes share comp)
#pragma unroll
    for (int off = 16; off >= 4; off >>= 1) {
        acc.x += __shfl_down_sync(0xffffffffu, acc.x, off);
        acc.y += __shfl_down_sync(0xffffffffu, acc.y, off);
        acc.z += __shfl_down_sync(0xffffffffu, acc.z, off);
        acc.w += __shfl_down_sync(0xffffffffu, acc.w, off);
    }
    if (lane < 4) {
        sMean[warp][lane * 4 + 0] = acc.x;
        sMean[warp][lane * 4 + 1] = acc.y;
        sMean[warp][lane * 4 + 2] = acc.z;
        sMean[warp][lane * 4 + 3] = acc.w;
    }
    __syncwarp();

    float invd = 1.0f / fmaxf((float)deg, 1.0f);
    float fv = 0.0f, mv = 0.0f;
    if (lane < 16) {
        fv = feat[(size_t)n * 16 + lane];
        mv = sMean[warp][lane] * invd;
    }

    float a0 = sb1[lane], a1 = sb1[lane + 32], a2 = sb1[lane + 64], a3 = sb1[lane + 96];
#pragma unroll
    for (int k = 0; k < 16; k++) {
        float fk = __shfl_sync(0xffffffffu, fv, k);
        float mk = __shfl_sync(0xffffffffu, mv, k);
        const float* wl = &sW1l[k * 128];
        const float* wr = &sW1r[k * 128];
        a0 = fmaf(mk, wl[lane],      fmaf(fk, wr[lane],      a0));
        a1 = fmaf(mk, wl[lane + 32], fmaf(fk, wr[lane + 32], a1));
        a2 = fmaf(mk, wl[lane + 64], fmaf(fk, wr[lane + 64], a2));
        a3 = fmaf(mk, wl[lane + 96], fmaf(fk, wr[lane + 96], a3));
    }
    a0 = fmaxf(a0, 0.0f); a1 = fmaxf(a1, 0.0f);
    a2 = fmaxf(a2, 0.0f); a3 = fmaxf(a3, 0.0f);

    float py[3], pz[3];
#pragma unroll
    for (int t = 0; t < 3; t++) {
        py[t] = a0 * sW2l[lane * 3 + t]
              + a1 * sW2l[(lane + 32) * 3 + t]
              + a2 * sW2l[(lane + 64) * 3 + t]
              + a3 * sW2l[(lane + 96) * 3 + t];
        pz[t] = a0 * sW2r[lane * 3 + t]
              + a1 * sW2r[(lane + 32) * 3 + t]
              + a2 * sW2r[(lane + 64) * 3 + t]
              + a3 * sW2r[(lane + 96) * 3 + t];
    }
#pragma unroll
    for (int off = 16; off > 0; off >>= 1) {
#pragma unroll
        for (int t = 0; t < 3; t++) {
            py[t] += __shfl_down_sync(0xffffffffu, py[t], off);
            pz[t] += __shfl_down_sync(0xffffffffu, pz[t], off);
        }
    }
    if (lane == 0) {
        *(float4*)&g_y[(size_t)n * 4] = make_float4(py[0], py[1], py[2], 0.0f);
        *(float4*)&g_z[(size_t)n * 4] = make_float4(pz[0], pz[1], pz[2], 0.0f);
    }
}

// ---------------------------------------------------------------------------
// 8) fused layer-2: gather-mean of y + epilogue. One warp per node.
// ---------------------------------------------------------------------------
__global__ void k_node2(const float* __restrict__ b2,
                        float* __restrict__ out, int N) {
    int gwarp = (blockIdx.x * blockDim.x + threadIdx.x) >> 5;
    int lane = threadIdx.x & 31;
    if (gwarp >= N) return;
    int n = gwarp;

    int deg = g_count[n];
    int start = g_start[n];

    float ax = 0.f, ay = 0.f, az = 0.f;
    for (int j = lane; j < deg; j += 32) {
        int src = g_perm_src[start + j];
        float4 v = *(const float4*)&g_y[(size_t)src * 4];
        ax += v.x; ay += v.y; az += v.z;
    }
#pragma unroll
    for (int off = 16; off > 0; off >>= 1) {
        ax += __shfl_down_sync(0xffffffffu, ax, off);
        ay += __shfl_down_sync(0xffffffffu, ay, off);
        az += __shfl_down_sync(0xffffffffu, az, off);
    }
    if (lane == 0) {
        float invd = 1.0f / fmaxf((float)deg, 1.0f);
        float4 z = *(const float4*)&g_z[(size_t)n * 4];
        out[(size_t)n * 3 + 0] = ax * invd + b2[0] + z.x;
        out[(size_t)n * 3 + 1] = ay * invd + b2[1] + z.y;
        out[(size_t)n * 3 + 2] = az * invd + b2[2] + z.z;
    }
}

// ---------------------------------------------------------------------------
extern "C" void kernel_launch(void* const* d_in, const int* in_sizes, int n_in,
                              void* d_out, int out_size) {
    const float* feature = (const float*)d_in[0];
    const int*   ei      = (const int*)d_in[1];   // int32 (JAX x64 disabled)
    // d_in[2] = edge_type (unused)
    const float* W1l = (const float*)d_in[3];
    const float* b1  = (const float*)d_in[4];
    const float* W1r = (const float*)d_in[5];
    const float* W2l = (const float*)d_in[6];
    const float* b2  = (const float*)d_in[7];
    const float* W2r = (const float*)d_in[8];
    float* out = (float*)d_out;

    int N = in_sizes[0] / 16;
    int E = in_sizes[1] / 2;
    int nb = (N + SCAN_B - 1) / SCAN_B;

    k_zero<<<(N + 255) / 256, 256>>>(N);
    k_hist<<<(E + 255) / 256, 256>>>(ei, E, N);
    k_scan1<<<nb, SCAN_B>>>(N);
    k_scan2<<<1, SCAN_B>>>(nb);
    k_scan3<<<(N + 255) / 256, 256>>>(N);
    k_scatter<<<(E + 255) / 256, 256>>>(ei, E, N);
    k_node1<<<(N * 32 + 255) / 256, 256>>>((const float4*)feature, feature,
                                           W1l, b1, W1r, W2l, W2r, N);
    k_node2<<<(N * 32 + 255) / 256, 256>>>(b2, out, N);
}

// round 6
// speedup vs baseline: 1.1300x; 1.1300x over previous
#include <cuda_runtime.h>
#include <cstdint>

#define MAX_NODES 100000
#define MAX_EDGES 1600000
#define SCAN_BLK 1024
#define MAX_SCAN_BLOCKS 128

// Scratch (static device globals; zero-initialized at load; node2 restores zeros)
__device__ int g_count[MAX_NODES];       // in-degree  (zeroed by node2 each run)
__device__ int g_cursor[MAX_NODES];      // scatter cursors (zeroed by node2 each run)
__device__ int g_start[MAX_NODES];       // CSR row starts
__device__ int g_perm_src[MAX_EDGES];    // src ids, dst-sorted
__device__ unsigned long long g_stat[MAX_SCAN_BLOCKS];  // scan status (zeroed by node2)
__device__ __align__(16) float g_y[MAX_NODES * 4];
__device__ __align__(16) float g_z[MAX_NODES * 4];

// ---------------------------------------------------------------------------
// 1) histogram of dst
// ---------------------------------------------------------------------------
__global__ void k_hist(const int* __restrict__ ei, int E, int N) {
    int e = blockIdx.x * blockDim.x + threadIdx.x;
    if (e >= E) return;
    int dst = __ldg(&ei[E + e]);
    if ((unsigned)dst < (unsigned)N) atomicAdd(&g_count[dst], 1);
}

// ---------------------------------------------------------------------------
// 2) single-pass exclusive scan of g_count -> g_start (decoupled lookback)
//    nb <= 128 blocks, all resident simultaneously -> no deadlock risk.
// ---------------------------------------------------------------------------
__device__ __forceinline__ void stat_store(unsigned long long* p, unsigned long long v) {
    asm volatile("st.global.release.gpu.u64 [%0], %1;" :: "l"(p), "l"(v) : "memory");
}
__device__ __forceinline__ unsigned long long stat_load(const unsigned long long* p) {
    unsigned long long v;
    asm volatile("ld.global.acquire.gpu.u64 %0, [%1];" : "=l"(v) : "l"(p) : "memory");
    return v;
}

__global__ void __launch_bounds__(SCAN_BLK) k_scan(int N) {
    __shared__ int wsum[32];
    __shared__ int s_base;
    int tid = threadIdx.x, bid = blockIdx.x;
    int lane = tid & 31, wid = tid >> 5;
    int i = bid * SCAN_BLK + tid;
    int v = (i < N) ? g_count[i] : 0;

    // warp inclusive scan
    int incl = v;
#pragma unroll
    for (int off = 1; off < 32; off <<= 1) {
        int t = __shfl_up_sync(0xffffffffu, incl, off);
        if (lane >= off) incl += t;
    }
    if (lane == 31) wsum[wid] = incl;
    __syncthreads();

    int total = 0;
    if (wid == 0) {
        int wv = wsum[lane];
        int winc = wv;
#pragma unroll
        for (int off = 1; off < 32; off <<= 1) {
            int t = __shfl_up_sync(0xffffffffu, winc, off);
            if (lane >= off) winc += t;
        }
        wsum[lane] = winc - wv;                 // exclusive warp offsets
        total = __shfl_sync(0xffffffffu, winc, 31);
        // publish aggregate (or inclusive for block 0) ASAP
        if (lane == 0) {
            unsigned long long pk = ((unsigned long long)(unsigned)total << 32)
                                  | (bid == 0 ? 2ull : 1ull);
            stat_store(&g_stat[bid], pk);
            if (bid == 0) s_base = 0;
        }
        // lookback (warp-parallel) with backoff
        if (bid > 0) {
            int look = bid - 1;
            int running = 0;
            while (true) {
                int idx = look - lane;
                int flag, val;
                unsigned long long pk;
                while (true) {
                    if (idx >= 0) {
                        pk = stat_load(&g_stat[idx]);
                        flag = (int)(pk & 3ull);
                        val  = (int)(pk >> 32);
                    } else { flag = 2; val = 0; }
                    if (!__any_sync(0xffffffffu, flag == 0)) break;
                    __nanosleep(20);
                }
                unsigned m = __ballot_sync(0xffffffffu, flag == 2);
                int contrib;
                if (m) {
                    int first = __ffs(m) - 1;
                    contrib = (lane <= first) ? val : 0;
                } else {
                    contrib = val;
                }
#pragma unroll
                for (int off = 16; off > 0; off >>= 1)
                    contrib += __shfl_down_sync(0xffffffffu, contrib, off);
                contrib = __shfl_sync(0xffffffffu, contrib, 0);
                running += contrib;
                if (m) break;
                look -= 32;
            }
            if (lane == 0) {
                unsigned long long pk =
                    ((unsigned long long)(unsigned)(running + total) << 32) | 2ull;
                stat_store(&g_stat[bid], pk);
                s_base = running;
            }
        }
    }
    __syncthreads();
    if (i < N) g_start[i] = s_base + wsum[wid] + (incl - v);
}

// ---------------------------------------------------------------------------
// 3) scatter src ids into dst-sorted order
// ---------------------------------------------------------------------------
__global__ void k_scatter(const int* __restrict__ ei, int E, int N) {
    int e = blockIdx.x * blockDim.x + threadIdx.x;
    if (e >= E) return;
    int src = __ldg(&ei[e]);
    int dst = __ldg(&ei[E + e]);
    if ((unsigned)src >= (unsigned)N || (unsigned)dst >= (unsigned)N) return;
    int pos = g_start[dst] + atomicAdd(&g_cursor[dst], 1);
    g_perm_src[pos] = src;
}

// ---------------------------------------------------------------------------
// 4) fused layer-1:
//    mean-gather + x1 = relu(mean@W1l + b1 + f@W1r), fold y=x1@W2l, z=x1@W2r.
//    One warp per node. No smem weights (L1-cached __ldg), 512B smem only.
//    Lane owns output cols 4*lane .. 4*lane+3 (float4 weight loads).
// ---------------------------------------------------------------------------
__global__ void __launch_bounds__(256) k_node1(
        const float4* __restrict__ feat4,
        const float*  __restrict__ feat,
        const float4* __restrict__ W1l4,   // 16 x 32 float4
        const float4* __restrict__ b1_4,   // 32 float4
        const float4* __restrict__ W1r4,   // 16 x 32 float4
        const float4* __restrict__ W2l4,   // 96 float4 (128x3 floats)
        const float4* __restrict__ W2r4,
        int N) {
    __shared__ float sMean[8][16];

    int tid = threadIdx.x;
    int lane = tid & 31;
    int warp = tid >> 5;
    int n = (blockIdx.x * blockDim.x + tid) >> 5;
    if (n >= N) return;

    int deg = g_count[n];
    int start = g_start[n];
    int egrp = lane >> 2;      // 0..7
    int comp = lane & 3;       // 0..3

    // gather: fetch up to 4 perm entries up-front (covers deg <= 32)
    int j0 = egrp, j1 = egrp + 8, j2 = egrp + 16, j3 = egrp + 24;
    int s0 = (j0 < deg) ? __ldg(&g_perm_src[start + j0]) : -1;
    int s1 = (j1 < deg) ? __ldg(&g_perm_src[start + j1]) : -1;
    int s2 = (j2 < deg) ? __ldg(&g_perm_src[start + j2]) : -1;
    int s3 = (j3 < deg) ? __ldg(&g_perm_src[start + j3]) : -1;

    float4 acc = make_float4(0.f, 0.f, 0.f, 0.f);
    if (s0 >= 0) { float4 v = __ldg(&feat4[(size_t)s0 * 4 + comp]);
                   acc.x += v.x; acc.y += v.y; acc.z += v.z; acc.w += v.w; }
    if (s1 >= 0) { float4 v = __ldg(&feat4[(size_t)s1 * 4 + comp]);
                   acc.x += v.x; acc.y += v.y; acc.z += v.z; acc.w += v.w; }
    if (s2 >= 0) { float4 v = __ldg(&feat4[(size_t)s2 * 4 + comp]);
                   acc.x += v.x; acc.y += v.y; acc.z += v.z; acc.w += v.w; }
    if (s3 >= 0) { float4 v = __ldg(&feat4[(size_t)s3 * 4 + comp]);
                   acc.x += v.x; acc.y += v.y; acc.z += v.z; acc.w += v.w; }
    // rare tail (deg > 32)
    for (int j = 32 + egrp; j < deg; j += 8) {
        int s = __ldg(&g_perm_src[start + j]);
        float4 v = __ldg(&feat4[(size_t)s * 4 + comp]);
        acc.x += v.x; acc.y += v.y; acc.z += v.z; acc.w += v.w;
    }
#pragma unroll
    for (int off = 16; off >= 4; off >>= 1) {
        acc.x += __shfl_down_sync(0xffffffffu, acc.x, off);
        acc.y += __shfl_down_sync(0xffffffffu, acc.y, off);
        acc.z += __shfl_down_sync(0xffffffffu, acc.z, off);
        acc.w += __shfl_down_sync(0xffffffffu, acc.w, off);
    }
    if (lane < 4) {
        sMean[warp][lane * 4 + 0] = acc.x;
        sMean[warp][lane * 4 + 1] = acc.y;
        sMean[warp][lane * 4 + 2] = acc.z;
        sMean[warp][lane * 4 + 3] = acc.w;
    }
    __syncwarp();

    float invd = 1.0f / fmaxf((float)deg, 1.0f);
    float fv = 0.0f, mv = 0.0f;
    if (lane < 16) {
        fv = __ldg(&feat[(size_t)n * 16 + lane]);
        mv = sMean[warp][lane] * invd;
    }

    float4 a = __ldg(&b1_4[lane]);
#pragma unroll
    for (int k = 0; k < 16; k++) {
        float fk = __shfl_sync(0xffffffffu, fv, k);
        float mk = __shfl_sync(0xffffffffu, mv, k);
        float4 wl = __ldg(&W1l4[k * 32 + lane]);
        float4 wr = __ldg(&W1r4[k * 32 + lane]);
        a.x = fmaf(mk, wl.x, fmaf(fk, wr.x, a.x));
        a.y = fmaf(mk, wl.y, fmaf(fk, wr.y, a.y));
        a.z = fmaf(mk, wl.z, fmaf(fk, wr.z, a.z));
        a.w = fmaf(mk, wl.w, fmaf(fk, wr.w, a.w));
    }
    a.x = fmaxf(a.x, 0.f); a.y = fmaxf(a.y, 0.f);
    a.z = fmaxf(a.z, 0.f); a.w = fmaxf(a.w, 0.f);

    // fold to y (W2l) and z (W2r): rows 4*lane..4*lane+3, 12 floats = 3 float4
    float4 l0 = __ldg(&W2l4[lane * 3 + 0]);
    float4 l1 = __ldg(&W2l4[lane * 3 + 1]);
    float4 l2 = __ldg(&W2l4[lane * 3 + 2]);
    float4 r0 = __ldg(&W2r4[lane * 3 + 0]);
    float4 r1 = __ldg(&W2r4[lane * 3 + 1]);
    float4 r2 = __ldg(&W2r4[lane * 3 + 2]);

    float py0 = a.x * l0.x + a.y * l0.w + a.z * l1.z + a.w * l2.y;
    float py1 = a.x * l0.y + a.y * l1.x + a.z * l1.w + a.w * l2.z;
    float py2 = a.x * l0.z + a.y * l1.y + a.z * l2.x + a.w * l2.w;
    float pz0 = a.x * r0.x + a.y * r0.w + a.z * r1.z + a.w * r2.y;
    float pz1 = a.x * r0.y + a.y * r1.x + a.z * r1.w + a.w * r2.z;
    float pz2 = a.x * r0.z + a.y * r1.y + a.z * r2.x + a.w * r2.w;

#pragma unroll
    for (int off = 16; off > 0; off >>= 1) {
        py0 += __shfl_down_sync(0xffffffffu, py0, off);
        py1 += __shfl_down_sync(0xffffffffu, py1, off);
        py2 += __shfl_down_sync(0xffffffffu, py2, off);
        pz0 += __shfl_down_sync(0xffffffffu, pz0, off);
        pz1 += __shfl_down_sync(0xffffffffu, pz1, off);
        pz2 += __shfl_down_sync(0xffffffffu, pz2, off);
    }
    if (lane == 0) {
        *(float4*)&g_y[(size_t)n * 4] = make_float4(py0, py1, py2, 0.f);
        *(float4*)&g_z[(size_t)n * 4] = make_float4(pz0, pz1, pz2, 0.f);
    }
}

// ---------------------------------------------------------------------------
// 5) fused layer-2: gather-mean of y + epilogue. Also restores zero-invariant
//    (g_count, g_cursor, g_stat) for the next graph replay.
// ---------------------------------------------------------------------------
__global__ void __launch_bounds__(256) k_node2(const float* __restrict__ b2,
                                               float* __restrict__ out, int N) {
    int tid = threadIdx.x;
    int lane = tid & 31;
    int n = (blockIdx.x * blockDim.x + tid) >> 5;
    if (tid == 0 && blockIdx.x < MAX_SCAN_BLOCKS) g_stat[blockIdx.x] = 0ull;
    if (n >= N) return;

    int deg = g_count[n];
    int start = g_start[n];

    float ax = 0.f, ay = 0.f, az = 0.f;
    for (int j = lane; j < deg; j += 32) {
        int src = __ldg(&g_perm_src[start + j]);
        float4 v = *(const float4*)&g_y[(size_t)src * 4];
        ax += v.x; ay += v.y; az += v.z;
    }
#pragma unroll
    for (int off = 16; off > 0; off >>= 1) {
        ax += __shfl_down_sync(0xffffffffu, ax, off);
        ay += __shfl_down_sync(0xffffffffu, ay, off);
        az += __shfl_down_sync(0xffffffffu, az, off);
    }
    if (lane == 0) {
        float invd = 1.0f / fmaxf((float)deg, 1.0f);
        float4 z = *(const float4*)&g_z[(size_t)n * 4];
        out[(size_t)n * 3 + 0] = ax * invd + __ldg(&b2[0]) + z.x;
        out[(size_t)n * 3 + 1] = ay * invd + __ldg(&b2[1]) + z.y;
        out[(size_t)n * 3 + 2] = az * invd + __ldg(&b2[2]) + z.z;
        g_count[n] = 0;      // restore zero-invariant for next replay
        g_cursor[n] = 0;
    }
}

// ---------------------------------------------------------------------------
extern "C" void kernel_launch(void* const* d_in, const int* in_sizes, int n_in,
                              void* d_out, int out_size) {
    const float* feature = (const float*)d_in[0];
    const int*   ei      = (const int*)d_in[1];   // int32 (JAX x64 disabled)
    // d_in[2] = edge_type (unused)
    const float* W1l = (const float*)d_in[3];
    const float* b1  = (const float*)d_in[4];
    const float* W1r = (const float*)d_in[5];
    const float* W2l = (const float*)d_in[6];
    const float* b2  = (const float*)d_in[7];
    const float* W2r = (const float*)d_in[8];
    float* out = (float*)d_out;

    int N = in_sizes[0] / 16;
    int E = in_sizes[1] / 2;
    int nb = (N + SCAN_BLK - 1) / SCAN_BLK;

    k_hist<<<(E + 255) / 256, 256>>>(ei, E, N);
    k_scan<<<nb, SCAN_BLK>>>(N);
    k_scatter<<<(E + 255) / 256, 256>>>(ei, E, N);
    k_node1<<<(N * 32 + 255) / 256, 256>>>((const float4*)feature, feature,
                                           (const float4*)W1l, (const float4*)b1,
                                           (const float4*)W1r, (const float4*)W2l,
                                           (const float4*)W2r, N);
    k_node2<<<(N * 32 + 255) / 256, 256>>>(b2, out, N);
}

// round 7
// speedup vs baseline: 1.4641x; 1.2956x over previous
#include <cuda_runtime.h>
#include <cstdint>

#define MAX_NODES 100000
#define MAX_EDGES 1600000
#define SCAN_BLK 1024
#define MAX_SCAN_BLOCKS 128

// Scratch (static device globals; zero-initialized at load; node2 restores zeros)
__device__ int g_count[MAX_NODES];
__device__ int g_cursor[MAX_NODES];
__device__ int g_start[MAX_NODES];
__device__ int g_perm_src[MAX_EDGES];
__device__ unsigned long long g_stat[MAX_SCAN_BLOCKS];
__device__ __align__(16) float g_y[MAX_NODES * 4];
__device__ __align__(16) float g_z[MAX_NODES * 4];

// ---------------------------------------------------------------------------
// 1) histogram of dst
// ---------------------------------------------------------------------------
__global__ void k_hist(const int* __restrict__ ei, int E, int N) {
    int e = blockIdx.x * blockDim.x + threadIdx.x;
    if (e >= E) return;
    int dst = __ldg(&ei[E + e]);
    if ((unsigned)dst < (unsigned)N) atomicAdd(&g_count[dst], 1);
}

// ---------------------------------------------------------------------------
// 2) single-pass exclusive scan (decoupled lookback), nb <= 128 blocks
// ---------------------------------------------------------------------------
__device__ __forceinline__ void stat_store(unsigned long long* p, unsigned long long v) {
    asm volatile("st.global.release.gpu.u64 [%0], %1;" :: "l"(p), "l"(v) : "memory");
}
__device__ __forceinline__ unsigned long long stat_load(const unsigned long long* p) {
    unsigned long long v;
    asm volatile("ld.global.acquire.gpu.u64 %0, [%1];" : "=l"(v) : "l"(p) : "memory");
    return v;
}

__global__ void __launch_bounds__(SCAN_BLK) k_scan(int N) {
    __shared__ int wsum[32];
    __shared__ int s_base;
    int tid = threadIdx.x, bid = blockIdx.x;
    int lane = tid & 31, wid = tid >> 5;
    int i = bid * SCAN_BLK + tid;
    int v = (i < N) ? g_count[i] : 0;

    int incl = v;
#pragma unroll
    for (int off = 1; off < 32; off <<= 1) {
        int t = __shfl_up_sync(0xffffffffu, incl, off);
        if (lane >= off) incl += t;
    }
    if (lane == 31) wsum[wid] = incl;
    __syncthreads();

    int total = 0;
    if (wid == 0) {
        int wv = wsum[lane];
        int winc = wv;
#pragma unroll
        for (int off = 1; off < 32; off <<= 1) {
            int t = __shfl_up_sync(0xffffffffu, winc, off);
            if (lane >= off) winc += t;
        }
        wsum[lane] = winc - wv;
        total = __shfl_sync(0xffffffffu, winc, 31);
        if (lane == 0) {
            unsigned long long pk = ((unsigned long long)(unsigned)total << 32)
                                  | (bid == 0 ? 2ull : 1ull);
            stat_store(&g_stat[bid], pk);
            if (bid == 0) s_base = 0;
        }
        if (bid > 0) {
            int look = bid - 1;
            int running = 0;
            while (true) {
                int idx = look - lane;
                int flag, val;
                unsigned long long pk;
                while (true) {
                    if (idx >= 0) {
                        pk = stat_load(&g_stat[idx]);
                        flag = (int)(pk & 3ull);
                        val  = (int)(pk >> 32);
                    } else { flag = 2; val = 0; }
                    if (!__any_sync(0xffffffffu, flag == 0)) break;
                    __nanosleep(20);
                }
                unsigned m = __ballot_sync(0xffffffffu, flag == 2);
                int contrib;
                if (m) {
                    int first = __ffs(m) - 1;
                    contrib = (lane <= first) ? val : 0;
                } else {
                    contrib = val;
                }
#pragma unroll
                for (int off = 16; off > 0; off >>= 1)
                    contrib += __shfl_down_sync(0xffffffffu, contrib, off);
                contrib = __shfl_sync(0xffffffffu, contrib, 0);
                running += contrib;
                if (m) break;
                look -= 32;
            }
            if (lane == 0) {
                unsigned long long pk =
                    ((unsigned long long)(unsigned)(running + total) << 32) | 2ull;
                stat_store(&g_stat[bid], pk);
                s_base = running;
            }
        }
    }
    __syncthreads();
    if (i < N) g_start[i] = s_base + wsum[wid] + (incl - v);
}

// ---------------------------------------------------------------------------
// 3) scatter src ids into dst-sorted order
// ---------------------------------------------------------------------------
__global__ void k_scatter(const int* __restrict__ ei, int E, int N) {
    int e = blockIdx.x * blockDim.x + threadIdx.x;
    if (e >= E) return;
    int src = __ldg(&ei[e]);
    int dst = __ldg(&ei[E + e]);
    if ((unsigned)src >= (unsigned)N || (unsigned)dst >= (unsigned)N) return;
    int pos = g_start[dst] + atomicAdd(&g_cursor[dst], 1);
    g_perm_src[pos] = src;
}

// ---------------------------------------------------------------------------
// 4) fused layer-1, node-tiled GEMM. Block = 256 thr = 8 warps = 64 nodes.
//    Phase 1 (gather): lane = (local node l>>2, comp l&3); each lane privately
//      sums one float4 quarter-row over all edges of its node; mean+feat -> smem.
//    Phase 2 (GEMM): warp computes 8 nodes x 128 cols; W1 float4 loaded ONCE
//      per k and reused for 8 nodes (8x less L1 weight traffic).
//    Phase 3: relu, fold to y=x1@W2l / z=x1@W2r, butterfly-reduce, store.
// ---------------------------------------------------------------------------
__global__ void __launch_bounds__(256) k_node1(
        const float4* __restrict__ feat4,
        const float4* __restrict__ W1l4,   // 16 x 32 float4
        const float4* __restrict__ b1_4,   // 32 float4
        const float4* __restrict__ W1r4,   // 16 x 32 float4
        const float4* __restrict__ W2l4,   // 96 float4
        const float4* __restrict__ W2r4,
        int N) {
    __shared__ __align__(16) float sM[64 * 16];   // means (already /deg)
    __shared__ __align__(16) float sF[64 * 16];   // self features

    int tid = threadIdx.x;
    int lane = tid & 31;
    int warp = tid >> 5;
    int tloc = lane >> 2;                 // local node within warp: 0..7
    int comp = lane & 3;                  // float4 quarter: 0..3
    int lnode = warp * 8 + tloc;          // local node within block: 0..63
    int n0 = blockIdx.x * 64;             // block's first node
    int n = n0 + lnode;

    // ---- phase 1: gather ----
    if (n < N) {
        int deg = g_count[n];
        int start = g_start[n];
        float4 f = __ldg(&feat4[(size_t)n * 4 + comp]);
        *(float4*)&sF[lnode * 16 + comp * 4] = f;

        float4 acc = make_float4(0.f, 0.f, 0.f, 0.f);
        int j = 0;
        for (; j + 3 < deg; j += 4) {
            int s0 = __ldg(&g_perm_src[start + j]);
            int s1 = __ldg(&g_perm_src[start + j + 1]);
            int s2 = __ldg(&g_perm_src[start + j + 2]);
            int s3 = __ldg(&g_perm_src[start + j + 3]);
            float4 v0 = __ldg(&feat4[(size_t)s0 * 4 + comp]);
            float4 v1 = __ldg(&feat4[(size_t)s1 * 4 + comp]);
            float4 v2 = __ldg(&feat4[(size_t)s2 * 4 + comp]);
            float4 v3 = __ldg(&feat4[(size_t)s3 * 4 + comp]);
            acc.x += v0.x + v1.x + v2.x + v3.x;
            acc.y += v0.y + v1.y + v2.y + v3.y;
            acc.z += v0.z + v1.z + v2.z + v3.z;
            acc.w += v0.w + v1.w + v2.w + v3.w;
        }
        for (; j < deg; j++) {
            int s = __ldg(&g_perm_src[start + j]);
            float4 v = __ldg(&feat4[(size_t)s * 4 + comp]);
            acc.x += v.x; acc.y += v.y; acc.z += v.z; acc.w += v.w;
        }
        float invd = 1.0f / fmaxf((float)deg, 1.0f);
        acc.x *= invd; acc.y *= invd; acc.z *= invd; acc.w *= invd;
        *(float4*)&sM[lnode * 16 + comp * 4] = acc;
    }
    __syncthreads();

    // ---- phase 2: tiled GEMM, 8 nodes per warp ----
    int nbase = warp * 8;                 // local node base for this warp
    float4 bb = __ldg(&b1_4[lane]);
    float4 a[8];
#pragma unroll
    for (int t = 0; t < 8; t++) a[t] = bb;

#pragma unroll 4
    for (int k = 0; k < 16; k++) {
        float4 wl = __ldg(&W1l4[k * 32 + lane]);
        float4 wr = __ldg(&W1r4[k * 32 + lane]);
#pragma unroll
        for (int t = 0; t < 8; t++) {
            float mk = sM[(nbase + t) * 16 + k];
            float fk = sF[(nbase + t) * 16 + k];
            a[t].x = fmaf(mk, wl.x, fmaf(fk, wr.x, a[t].x));
            a[t].y = fmaf(mk, wl.y, fmaf(fk, wr.y, a[t].y));
            a[t].z = fmaf(mk, wl.z, fmaf(fk, wr.z, a[t].z));
            a[t].w = fmaf(mk, wl.w, fmaf(fk, wr.w, a[t].w));
        }
    }

    // ---- phase 3: relu + fold + reduce + store ----
    float4 l0 = __ldg(&W2l4[lane * 3 + 0]);
    float4 l1 = __ldg(&W2l4[lane * 3 + 1]);
    float4 l2 = __ldg(&W2l4[lane * 3 + 2]);
    float4 r0 = __ldg(&W2r4[lane * 3 + 0]);
    float4 r1 = __ldg(&W2r4[lane * 3 + 1]);
    float4 r2 = __ldg(&W2r4[lane * 3 + 2]);

#pragma unroll
    for (int t = 0; t < 8; t++) {
        float ax = fmaxf(a[t].x, 0.f), ay = fmaxf(a[t].y, 0.f);
        float az = fmaxf(a[t].z, 0.f), aw = fmaxf(a[t].w, 0.f);

        float py0 = ax * l0.x + ay * l0.w + az * l1.z + aw * l2.y;
        float py1 = ax * l0.y + ay * l1.x + az * l1.w + aw * l2.z;
        float py2 = ax * l0.z + ay * l1.y + az * l2.x + aw * l2.w;
        float pz0 = ax * r0.x + ay * r0.w + az * r1.z + aw * r2.y;
        float pz1 = ax * r0.y + ay * r1.x + az * r1.w + aw * r2.z;
        float pz2 = ax * r0.z + ay * r1.y + az * r2.x + aw * r2.w;

#pragma unroll
        for (int off = 16; off > 0; off >>= 1) {
            py0 += __shfl_down_sync(0xffffffffu, py0, off);
            py1 += __shfl_down_sync(0xffffffffu, py1, off);
            py2 += __shfl_down_sync(0xffffffffu, py2, off);
            pz0 += __shfl_down_sync(0xffffffffu, pz0, off);
            pz1 += __shfl_down_sync(0xffffffffu, pz1, off);
            pz2 += __shfl_down_sync(0xffffffffu, pz2, off);
        }
        int nn = n0 + nbase + t;
        if (lane == 0 && nn < N) {
            *(float4*)&g_y[(size_t)nn * 4] = make_float4(py0, py1, py2, 0.f);
            *(float4*)&g_z[(size_t)nn * 4] = make_float4(pz0, pz1, pz2, 0.f);
        }
    }
}

// ---------------------------------------------------------------------------
// 5) fused layer-2: gather-mean of y + epilogue; restores zero-invariant.
// ---------------------------------------------------------------------------
__global__ void __launch_bounds__(256) k_node2(const float* __restrict__ b2,
                                               float* __restrict__ out, int N) {
    int tid = threadIdx.x;
    int lane = tid & 31;
    int n = (blockIdx.x * blockDim.x + tid) >> 5;
    if (tid == 0 && blockIdx.x < MAX_SCAN_BLOCKS) g_stat[blockIdx.x] = 0ull;
    if (n >= N) return;

    int deg = g_count[n];
    int start = g_start[n];

    float ax = 0.f, ay = 0.f, az = 0.f;
    for (int j = lane; j < deg; j += 32) {
        int src = __ldg(&g_perm_src[start + j]);
        float4 v = *(const float4*)&g_y[(size_t)src * 4];
        ax += v.x; ay += v.y; az += v.z;
    }
#pragma unroll
    for (int off = 16; off > 0; off >>= 1) {
        ax += __shfl_down_sync(0xffffffffu, ax, off);
        ay += __shfl_down_sync(0xffffffffu, ay, off);
        az += __shfl_down_sync(0xffffffffu, az, off);
    }
    if (lane == 0) {
        float invd = 1.0f / fmaxf((float)deg, 1.0f);
        float4 z = *(const float4*)&g_z[(size_t)n * 4];
        out[(size_t)n * 3 + 0] = ax * invd + __ldg(&b2[0]) + z.x;
        out[(size_t)n * 3 + 1] = ay * invd + __ldg(&b2[1]) + z.y;
        out[(size_t)n * 3 + 2] = az * invd + __ldg(&b2[2]) + z.z;
        g_count[n] = 0;
        g_cursor[n] = 0;
    }
}

// ---------------------------------------------------------------------------
extern "C" void kernel_launch(void* const* d_in, const int* in_sizes, int n_in,
                              void* d_out, int out_size) {
    const float* feature = (const float*)d_in[0];
    const int*   ei      = (const int*)d_in[1];   // int32 (JAX x64 disabled)
    // d_in[2] = edge_type (unused)
    const float* W1l = (const float*)d_in[3];
    const float* b1  = (const float*)d_in[4];
    const float* W1r = (const float*)d_in[5];
    const float* W2l = (const float*)d_in[6];
    const float* b2  = (const float*)d_in[7];
    const float* W2r = (const float*)d_in[8];
    float* out = (float*)d_out;

    int N = in_sizes[0] / 16;
    int E = in_sizes[1] / 2;
    int nb = (N + SCAN_BLK - 1) / SCAN_BLK;

    k_hist<<<(E + 255) / 256, 256>>>(ei, E, N);
    k_scan<<<nb, SCAN_BLK>>>(N);
    k_scatter<<<(E + 255) / 256, 256>>>(ei, E, N);
    k_node1<<<(N + 63) / 64, 256>>>((const float4*)feature,
                                    (const float4*)W1l, (const float4*)b1,
                                    (const float4*)W1r, (const float4*)W2l,
                                    (const float4*)W2r, N);
    k_node2<<<(N * 32 + 255) / 256, 256>>>(b2, out, N);
}

// round 11
// speedup vs baseline: 1.6950x; 1.1578x over previous
#include <cuda_runtime.h>
#include <cstdint>

#define MAX_NODES 100000
#define MAX_EDGES 1600000
#define SCAN_BLK 1024
#define MAX_SCAN_BLOCKS 128

// Scratch (static device globals; zero-initialized at load; node2 restores zeros)
__device__ int g_count[MAX_NODES];
__device__ int g_cursor[MAX_NODES];
__device__ int g_start[MAX_NODES];
__device__ int g_perm_src[MAX_EDGES];
__device__ unsigned long long g_stat[MAX_SCAN_BLOCKS];
__device__ __align__(16) float4 g_mean[MAX_NODES * 4];   // mean feature, 16 f/node
__device__ __align__(16) float g_y[MAX_NODES * 4];
__device__ __align__(16) float g_z[MAX_NODES * 4];

// ---------------------------------------------------------------------------
// 1) histogram of dst
// ---------------------------------------------------------------------------
__global__ void k_hist(const int* __restrict__ ei, int E, int N) {
    int e = blockIdx.x * blockDim.x + threadIdx.x;
    if (e >= E) return;
    int dst = __ldg(&ei[E + e]);
    if ((unsigned)dst < (unsigned)N) atomicAdd(&g_count[dst], 1);
}

// ---------------------------------------------------------------------------
// 2) single-pass exclusive scan (decoupled lookback), nb <= 128 blocks
// ---------------------------------------------------------------------------
__device__ __forceinline__ void stat_store(unsigned long long* p, unsigned long long v) {
    asm volatile("st.global.release.gpu.u64 [%0], %1;" :: "l"(p), "l"(v) : "memory");
}
__device__ __forceinline__ unsigned long long stat_load(const unsigned long long* p) {
    unsigned long long v;
    asm volatile("ld.global.acquire.gpu.u64 %0, [%1];" : "=l"(v) : "l"(p) : "memory");
    return v;
}

__global__ void __launch_bounds__(SCAN_BLK) k_scan(int N) {
    __shared__ int wsum[32];
    __shared__ int s_base;
    int tid = threadIdx.x, bid = blockIdx.x;
    int lane = tid & 31, wid = tid >> 5;
    int i = bid * SCAN_BLK + tid;
    int v = (i < N) ? g_count[i] : 0;

    int incl = v;
#pragma unroll
    for (int off = 1; off < 32; off <<= 1) {
        int t = __shfl_up_sync(0xffffffffu, incl, off);
        if (lane >= off) incl += t;
    }
    if (lane == 31) wsum[wid] = incl;
    __syncthreads();

    int total = 0;
    if (wid == 0) {
        int wv = wsum[lane];
        int winc = wv;
#pragma unroll
        for (int off = 1; off < 32; off <<= 1) {
            int t = __shfl_up_sync(0xffffffffu, winc, off);
            if (lane >= off) winc += t;
        }
        wsum[lane] = winc - wv;
        total = __shfl_sync(0xffffffffu, winc, 31);
        if (lane == 0) {
            unsigned long long pk = ((unsigned long long)(unsigned)total << 32)
                                  | (bid == 0 ? 2ull : 1ull);
            stat_store(&g_stat[bid], pk);
            if (bid == 0) s_base = 0;
        }
        if (bid > 0) {
            int look = bid - 1;
            int running = 0;
            while (true) {
                int idx = look - lane;
                int flag, val;
                unsigned long long pk;
                while (true) {
                    if (idx >= 0) {
                        pk = stat_load(&g_stat[idx]);
                        flag = (int)(pk & 3ull);
                        val  = (int)(pk >> 32);
                    } else { flag = 2; val = 0; }
                    if (!__any_sync(0xffffffffu, flag == 0)) break;
                    __nanosleep(20);
                }
                unsigned m = __ballot_sync(0xffffffffu, flag == 2);
                int contrib;
                if (m) {
                    int first = __ffs(m) - 1;
                    contrib = (lane <= first) ? val : 0;
                } else {
                    contrib = val;
                }
#pragma unroll
                for (int off = 16; off > 0; off >>= 1)
                    contrib += __shfl_down_sync(0xffffffffu, contrib, off);
                contrib = __shfl_sync(0xffffffffu, contrib, 0);
                running += contrib;
                if (m) break;
                look -= 32;
            }
            if (lane == 0) {
                unsigned long long pk =
                    ((unsigned long long)(unsigned)(running + total) << 32) | 2ull;
                stat_store(&g_stat[bid], pk);
                s_base = running;
            }
        }
    }
    __syncthreads();
    if (i < N) g_start[i] = s_base + wsum[wid] + (incl - v);
}

// ---------------------------------------------------------------------------
// 3) scatter src ids into dst-sorted order
// ---------------------------------------------------------------------------
__global__ void k_scatter(const int* __restrict__ ei, int E, int N) {
    int e = blockIdx.x * blockDim.x + threadIdx.x;
    if (e >= E) return;
    int src = __ldg(&ei[e]);
    int dst = __ldg(&ei[E + e]);
    if ((unsigned)src >= (unsigned)N || (unsigned)dst >= (unsigned)N) return;
    int pos = g_start[dst] + atomicAdd(&g_cursor[dst], 1);
    g_perm_src[pos] = src;
}

// ---------------------------------------------------------------------------
// 4a) gather-mean: 4 lanes per node, each owns one float4 quarter-row.
//     Low regs -> full occupancy; pure L1/L2 streaming.
// ---------------------------------------------------------------------------
__global__ void __launch_bounds__(256) k_gather(const float4* __restrict__ feat4,
                                                int N) {
    long long gid = (long long)blockIdx.x * blockDim.x + threadIdx.x;
    int n = (int)(gid >> 2);
    int comp = (int)(gid & 3);
    if (n >= N) return;

    int deg = g_count[n];
    int start = g_start[n];

    float4 acc = make_float4(0.f, 0.f, 0.f, 0.f);
    int j = 0;
    for (; j + 3 < deg; j += 4) {
        int s0 = __ldg(&g_perm_src[start + j]);
        int s1 = __ldg(&g_perm_src[start + j + 1]);
        int s2 = __ldg(&g_perm_src[start + j + 2]);
        int s3 = __ldg(&g_perm_src[start + j + 3]);
        float4 v0 = __ldg(&feat4[(size_t)s0 * 4 + comp]);
        float4 v1 = __ldg(&feat4[(size_t)s1 * 4 + comp]);
        float4 v2 = __ldg(&feat4[(size_t)s2 * 4 + comp]);
        float4 v3 = __ldg(&feat4[(size_t)s3 * 4 + comp]);
        acc.x += v0.x + v1.x + v2.x + v3.x;
        acc.y += v0.y + v1.y + v2.y + v3.y;
        acc.z += v0.z + v1.z + v2.z + v3.z;
        acc.w += v0.w + v1.w + v2.w + v3.w;
    }
    for (; j < deg; j++) {
        int s = __ldg(&g_perm_src[start + j]);
        float4 v = __ldg(&feat4[(size_t)s * 4 + comp]);
        acc.x += v.x; acc.y += v.y; acc.z += v.z; acc.w += v.w;
    }
    float invd = 1.0f / fmaxf((float)deg, 1.0f);
    acc.x *= invd; acc.y *= invd; acc.z *= invd; acc.w *= invd;
    g_mean[(size_t)n * 4 + comp] = acc;
}

// ---------------------------------------------------------------------------
// 4b) GEMM + fold. Block = 256 thr = 8 warps = 64 nodes (8 per warp).
//     W1 staged in smem once per block; mean/feat staged via coalesced loads.
//     Lane owns cols 4*lane..4*lane+3; per k: 2 LDS.128 reused by 8 nodes.
// ---------------------------------------------------------------------------
__global__ void __launch_bounds__(256) k_gemm(
        const float4* __restrict__ feat4,
        const float4* __restrict__ W1l4,   // 16 x 32 float4
        const float4* __restrict__ b1_4,   // 32 float4
        const float4* __restrict__ W1r4,   // 16 x 32 float4
        const float4* __restrict__ W2l4,   // 96 float4
        const float4* __restrict__ W2r4,
        int N) {
    __shared__ __align__(16) float sW1l[16 * 128];
    __shared__ __align__(16) float sW1r[16 * 128];
    __shared__ __align__(16) float sMF[64 * 32];   // per node: [0..15]=mean, [16..31]=feat

    int tid = threadIdx.x;
    int lane = tid & 31;
    int warp = tid >> 5;
    int n0 = blockIdx.x * 64;

    // coop stage W1 (1024 float4s over 256 threads)
    {
        float4* dl = (float4*)sW1l;
        float4* dr = (float4*)sW1r;
#pragma unroll
        for (int i = 0; i < 2; i++) {
            dl[tid + i * 256] = __ldg(&W1l4[tid + i * 256]);
            dr[tid + i * 256] = __ldg(&W1r4[tid + i * 256]);
        }
    }
    // coop stage mean+feat: thread i -> node i>>2, comp i&3
    {
        int ln = tid >> 2, comp = tid & 3;
        int nn = n0 + ln;
        if (nn < N) {
            *(float4*)&sMF[ln * 32 + comp * 4]      = g_mean[(size_t)nn * 4 + comp];
            *(float4*)&sMF[ln * 32 + 16 + comp * 4] = __ldg(&feat4[(size_t)nn * 4 + comp]);
        }
    }
    __syncthreads();

    int nbase = warp * 8;
    float4 bb = __ldg(&b1_4[lane]);
    float4 a[8];
#pragma unroll
    for (int t = 0; t < 8; t++) a[t] = bb;

#pragma unroll
    for (int k = 0; k < 16; k++) {
        float4 wl = *(float4*)&sW1l[k * 128 + lane * 4];
        float4 wr = *(float4*)&sW1r[k * 128 + lane * 4];
#pragma unroll
        for (int t = 0; t < 8; t++) {
            float mk = sMF[(nbase + t) * 32 + k];
            float fk = sMF[(nbase + t) * 32 + 16 + k];
            a[t].x = fmaf(mk, wl.x, fmaf(fk, wr.x, a[t].x));
            a[t].y = fmaf(mk, wl.y, fmaf(fk, wr.y, a[t].y));
            a[t].z = fmaf(mk, wl.z, fmaf(fk, wr.z, a[t].z));
            a[t].w = fmaf(mk, wl.w, fmaf(fk, wr.w, a[t].w));
        }
    }

    // relu + fold to y/z + butterfly reduce + store
    float4 l0 = __ldg(&W2l4[lane * 3 + 0]);
    float4 l1 = __ldg(&W2l4[lane * 3 + 1]);
    float4 l2 = __ldg(&W2l4[lane * 3 + 2]);
    float4 r0 = __ldg(&W2r4[lane * 3 + 0]);
    float4 r1 = __ldg(&W2r4[lane * 3 + 1]);
    float4 r2 = __ldg(&W2r4[lane * 3 + 2]);

#pragma unroll
    for (int t = 0; t < 8; t++) {
        float ax = fmaxf(a[t].x, 0.f), ay = fmaxf(a[t].y, 0.f);
        float az = fmaxf(a[t].z, 0.f), aw = fmaxf(a[t].w, 0.f);

        float py0 = ax * l0.x + ay * l0.w + az * l1.z + aw * l2.y;
        float py1 = ax * l0.y + ay * l1.x + az * l1.w + aw * l2.z;
        float py2 = ax * l0.z + ay * l1.y + az * l2.x + aw * l2.w;
        float pz0 = ax * r0.x + ay * r0.w + az * r1.z + aw * r2.y;
        float pz1 = ax * r0.y + ay * r1.x + az * r1.w + aw * r2.z;
        float pz2 = ax * r0.z + ay * r1.y + az * r2.x + aw * r2.w;

#pragma unroll
        for (int off = 16; off > 0; off >>= 1) {
            py0 += __shfl_down_sync(0xffffffffu, py0, off);
            py1 += __shfl_down_sync(0xffffffffu, py1, off);
            py2 += __shfl_down_sync(0xffffffffu, py2, off);
            pz0 += __shfl_down_sync(0xffffffffu, pz0, off);
            pz1 += __shfl_down_sync(0xffffffffu, pz1, off);
            pz2 += __shfl_down_sync(0xffffffffu, pz2, off);
        }
        int nn = n0 + nbase + t;
        if (lane == 0 && nn < N) {
            *(float4*)&g_y[(size_t)nn * 4] = make_float4(py0, py1, py2, 0.f);
            *(float4*)&g_z[(size_t)nn * 4] = make_float4(pz0, pz1, pz2, 0.f);
        }
    }
}

// ---------------------------------------------------------------------------
// 5) fused layer-2: 8 lanes/node gather-mean of y + epilogue; restores zeros.
// ---------------------------------------------------------------------------
__global__ void __launch_bounds__(256) k_node2(const float* __restrict__ b2,
                                               float* __restrict__ out, int N) {
    int tid = threadIdx.x;
    if (tid == 0 && blockIdx.x < MAX_SCAN_BLOCKS) g_stat[blockIdx.x] = 0ull;
    long long gid = (long long)blockIdx.x * blockDim.x + tid;
    int n = (int)(gid >> 3);
    int sub = (int)(gid & 7);
    if (n >= N) return;

    int deg = g_count[n];
    int start = g_start[n];

    float ax = 0.f, ay = 0.f, az = 0.f;
    for (int j = sub; j < deg; j += 8) {
        int src = __ldg(&g_perm_src[start + j]);
        float4 v = *(const float4*)&g_y[(size_t)src * 4];
        ax += v.x; ay += v.y; az += v.z;
    }
#pragma unroll
    for (int off = 4; off > 0; off >>= 1) {
        ax += __shfl_down_sync(0xffffffffu, ax, off, 8);
        ay += __shfl_down_sync(0xffffffffu, ay, off, 8);
        az += __shfl_down_sync(0xffffffffu, az, off, 8);
    }
    if (sub == 0) {
        float invd = 1.0f / fmaxf((float)deg, 1.0f);
        float4 z = *(const float4*)&g_z[(size_t)n * 4];
        out[(size_t)n * 3 + 0] = ax * invd + __ldg(&b2[0]) + z.x;
        out[(size_t)n * 3 + 1] = ay * invd + __ldg(&b2[1]) + z.y;
        out[(size_t)n * 3 + 2] = az * invd + __ldg(&b2[2]) + z.z;
        g_count[n] = 0;
        g_cursor[n] = 0;
    }
}

// ---------------------------------------------------------------------------
extern "C" void kernel_launch(void* const* d_in, const int* in_sizes, int n_in,
                              void* d_out, int out_size) {
    const float* feature = (const float*)d_in[0];
    const int*   ei      = (const int*)d_in[1];   // int32 (JAX x64 disabled)
    // d_in[2] = edge_type (unused)
    const float* W1l = (const float*)d_in[3];
    const float* b1  = (const float*)d_in[4];
    const float* W1r = (const float*)d_in[5];
    const float* W2l = (const float*)d_in[6];
    const float* b2  = (const float*)d_in[7];
    const float* W2r = (const float*)d_in[8];
    float* out = (float*)d_out;

    int N = in_sizes[0] / 16;
    int E = in_sizes[1] / 2;
    int nb = (N + SCAN_BLK - 1) / SCAN_BLK;

    k_hist<<<(E + 255) / 256, 256>>>(ei, E, N);
    k_scan<<<nb, SCAN_BLK>>>(N);
    k_scatter<<<(E + 255) / 256, 256>>>(ei, E, N);
    k_gather<<<(int)((4LL * N + 255) / 256), 256>>>((const float4*)feature, N);
    k_gemm<<<(N + 63) / 64, 256>>>((const float4*)feature,
                                   (const float4*)W1l, (const float4*)b1,
                                   (const float4*)W1r, (const float4*)W2l,
                                   (const float4*)W2r, N);
    k_node2<<<(int)((8LL * N + 255) / 256), 256>>>(b2, out, N);
}